// round 15
// baseline (speedup 1.0000x reference)
#include <cuda_runtime.h>
#include <math.h>
#include <stdint.h>
#include <string.h>

// B=32, T=1024, D_IN=80, enc: 80->512->512->256 (ReLU), F=768, 4H=1024, H=256

// ------------------------- device scratch -------------------------
__device__ float d_h[32768 * 256];
__device__ float d_Z[32768 * 2048];        // [b][t][2048]: cols 0..1023 fwd, 1024..2047 bwd
__device__ float d_biascat[2048];
__device__ uint4 d_Hfrag[2][2][2048];      // [parity][dir][(((wid*2+mt)*2+kt)*2+hl)*32+lane]
__device__ float d_Hout[2][1024][256][32]; // [dir][t][k][b]
__device__ int d_order[32];
__device__ int d_lens[32];
__device__ unsigned d_ctr2[2];
// pre-converted bf16 hi/lo weights + activations
__device__ uint16_t d_Wch[2048 * 768], d_Wcl[2048 * 768];
__device__ uint16_t d_W1h[512 * 512], d_W1l[512 * 512];
__device__ uint16_t d_W2h[256 * 512], d_W2l[256 * 512];
__device__ uint16_t d_W0h[512 * 96], d_W0l[512 * 96];
__device__ uint16_t d_Xh[32768 * 96], d_Xl[32768 * 96];
__device__ uint16_t d_A0h[32768 * 512], d_A0l[32768 * 512];
__device__ uint16_t d_A1h[32768 * 512], d_A1l[32768 * 512];
__device__ uint16_t d_Fh[32768 * 768], d_Fl[32768 * 768];

// ------------------------- helpers -------------------------
__device__ __forceinline__ uint32_t s2u(const void* p) {
    uint32_t a;
    asm("{ .reg .u64 t; cvta.to.shared.u64 t, %1; cvt.u32.u64 %0, t; }" : "=r"(a) : "l"(p));
    return a;
}
__device__ __forceinline__ uint32_t cvt2bf(float lo, float hi) {
    uint32_t r;
    asm("cvt.rn.satfinite.bf16x2.f32 %0, %1, %2;" : "=r"(r) : "f"(hi), "f"(lo));
    return r;
}
__device__ __forceinline__ void pack2(float x0, float x1, uint32_t& ph, uint32_t& pl) {
    ph = cvt2bf(x0, x1);
    float r0 = x0 - __uint_as_float(ph << 16);
    float r1 = x1 - __uint_as_float(ph & 0xffff0000u);
    pl = cvt2bf(r0, r1);
}
__device__ __forceinline__ void ldsm4(uint32_t* r, uint32_t addr) {
    asm volatile("ldmatrix.sync.aligned.m8n8.x4.shared.b16 {%0,%1,%2,%3}, [%4];"
                 : "=r"(r[0]), "=r"(r[1]), "=r"(r[2]), "=r"(r[3]) : "r"(addr));
}
__device__ __forceinline__ void mma16816(float* c, const uint32_t* a, uint32_t b0, uint32_t b1) {
    asm volatile(
        "mma.sync.aligned.m16n8k16.row.col.f32.bf16.bf16.f32 "
        "{%0,%1,%2,%3}, {%4,%5,%6,%7}, {%8,%9}, {%0,%1,%2,%3};"
        : "+f"(c[0]), "+f"(c[1]), "+f"(c[2]), "+f"(c[3])
        : "r"(a[0]), "r"(a[1]), "r"(a[2]), "r"(a[3]), "r"(b0), "r"(b1));
}
__device__ __forceinline__ void cpasync16(uint32_t smem_dst, const void* gsrc) {
    asm volatile("cp.async.cg.shared.global [%0], [%1], 16;"
                 :: "r"(smem_dst), "l"(gsrc) : "memory");
}
#define SWZB(row, c) ((((uint32_t)(row)) << 6) + ((((uint32_t)(c) ^ (((uint32_t)(row) >> 1) & 3))) << 4))

// write (f0,f1) for (b, k0, k0+1) as mma A-fragment (hi + lo residual)
__device__ __forceinline__ void write_frag(int parity, int dir, int b, int k0, float f0, float f1) {
    uint32_t hi = cvt2bf(f0, f1);
    float r0 = f0 - __uint_as_float(hi << 16);
    float r1 = f1 - __uint_as_float(hi & 0xffff0000u);
    uint32_t lo = cvt2bf(r0, r1);
    int wd = k0 >> 5, kt = (k0 >> 4) & 1, jhi = (k0 >> 3) & 1, ll = (k0 >> 1) & 3;
    int mt = b >> 4, jlo = (b >> 3) & 1, L = (b & 7) * 4 + ll, j = jhi * 2 + jlo;
    uint32_t* H = (uint32_t*)&d_Hfrag[parity][dir][0];
    int base = ((wd * 2 + mt) * 2 + kt) * 2;
    H[(size_t)(((base + 0) * 32 + L) * 4 + j)] = hi;
    H[(size_t)(((base + 1) * 32 + L) * 4 + j)] = lo;
}

__device__ __forceinline__ void conv_range(const float* __restrict__ src,
                                           uint16_t* __restrict__ dh, uint16_t* __restrict__ dl,
                                           int npairs, int tid, int nth) {
    for (int i = tid; i < npairs; i += nth) {
        float2 v = ((const float2*)src)[i];
        uint32_t ph, pl;
        pack2(v.x, v.y, ph, pl);
        ((uint32_t*)dh)[i] = ph;
        ((uint32_t*)dl)[i] = pl;
    }
}

__device__ __forceinline__ void conv_pad(const float* __restrict__ src,
                                         uint16_t* __restrict__ dh, uint16_t* __restrict__ dl,
                                         int rows, int kreal, int kpad2, int tid, int nth) {
    const int rp = kreal >> 1;
    for (int i = tid; i < rows * kpad2; i += nth) {
        int row = i / kpad2, cp = i % kpad2;
        uint32_t ph = 0, pl = 0;
        if (cp < rp) {
            float2 v = *(const float2*)(src + (size_t)row * kreal + cp * 2);
            pack2(v.x, v.y, ph, pl);
        }
        ((uint32_t*)dh)[i] = ph;
        ((uint32_t*)dl)[i] = pl;
    }
}

// ------------------------- prep: order, biascat, all conversions -------------------------
__global__ void __launch_bounds__(256) prep_k(
    const float* __restrict__ x, const int* __restrict__ xlen,
    const float* __restrict__ W0, const float* __restrict__ W1, const float* __restrict__ W2,
    const float* __restrict__ Wihf, const float* __restrict__ Wihb,
    const float* __restrict__ bihf, const float* __restrict__ bhhf,
    const float* __restrict__ bihb, const float* __restrict__ bhhb) {
    const int ptid = blockIdx.x * 256 + threadIdx.x;
    const int nth = gridDim.x * 256;
    if (ptid == 0) {
        unsigned used = 0;
        for (int p = 0; p < 32; ++p) {
            int best = -1, bl = -2147483647;
            for (int j = 0; j < 32; ++j) {
                if (used & (1u << j)) continue;
                int L = xlen[j];
                if (L > bl) { bl = L; best = j; }
            }
            used |= (1u << best);
            d_order[p] = best;
            d_lens[p] = bl;
        }
        d_ctr2[0] = 0u;
        d_ctr2[1] = 0u;
    }
    if (ptid < 1024) d_biascat[ptid] = bihf[ptid] + bhhf[ptid];
    else if (ptid < 2048) d_biascat[ptid] = bihb[ptid - 1024] + bhhb[ptid - 1024];
    conv_pad(x, d_Xh, d_Xl, 32768, 80, 48, ptid, nth);
    conv_pad(W0, d_W0h, d_W0l, 512, 80, 48, ptid, nth);
    conv_range(W1, d_W1h, d_W1l, 131072, ptid, nth);
    conv_range(W2, d_W2h, d_W2l, 65536, ptid, nth);
    conv_range(Wihf, d_Wch, d_Wcl, 393216, ptid, nth);
    conv_range(Wihb, d_Wch + 1024 * 768, d_Wcl + 1024 * 768, 393216, ptid, nth);
}

// ------------------------- HMMA split-bf16 GEMM (cp.async staging, 2 CTAs/SM) ------------------
template <int RELU, int OUTBF>
__global__ void __launch_bounds__(256, 2) gemm_mma_k(
    const uint16_t* __restrict__ Ahi, const uint16_t* __restrict__ Alo,
    const uint16_t* __restrict__ Bhi, const uint16_t* __restrict__ Blo,
    const float* __restrict__ bias, float* __restrict__ Cf,
    uint16_t* __restrict__ Chi, uint16_t* __restrict__ Clo,
    int K, int ldo) {
    extern __shared__ char smc[];
    const int tid = threadIdx.x, lane = tid & 31, wid = tid >> 5;
    const int wm = wid >> 2, wn = wid & 3;
    const int n0 = blockIdx.x * 128, m0 = blockIdx.y * 128;
    const int NCH = K >> 5;
    const uint32_t sbase = s2u(smc);
    float* sBias = (float*)(smc + 65536);
    if (tid < 128) sBias[tid] = bias[n0 + tid];

    const int ra = tid >> 2, ca = tid & 3;
    const int ldu = K >> 3;
    const uint4* Ah0 = (const uint4*)Ahi + (size_t)(m0 + ra) * ldu + ca;
    const uint4* Al0 = (const uint4*)Alo + (size_t)(m0 + ra) * ldu + ca;
    const uint4* Ah1 = (const uint4*)Ahi + (size_t)(m0 + 64 + ra) * ldu + ca;
    const uint4* Al1 = (const uint4*)Alo + (size_t)(m0 + 64 + ra) * ldu + ca;
    const uint4* Bh0 = (const uint4*)Bhi + (size_t)(n0 + ra) * ldu + ca;
    const uint4* Bl0 = (const uint4*)Blo + (size_t)(n0 + ra) * ldu + ca;
    const uint4* Bh1 = (const uint4*)Bhi + (size_t)(n0 + 64 + ra) * ldu + ca;
    const uint4* Bl1 = (const uint4*)Blo + (size_t)(n0 + 64 + ra) * ldu + ca;

    float acc[4][4][4];
#pragma unroll
    for (int mi = 0; mi < 4; mi++)
#pragma unroll
        for (int j = 0; j < 4; j++)
#pragma unroll
            for (int q = 0; q < 4; q++) acc[mi][j][q] = 0.f;

    const uint32_t o0 = SWZB(ra, ca), o1 = SWZB(64 + ra, ca);
    {
        uint32_t base = sbase;
        cpasync16(base + o0, Ah0);
        cpasync16(base + 8192 + o0, Al0);
        cpasync16(base + o1, Ah1);
        cpasync16(base + 8192 + o1, Al1);
        cpasync16(base + 16384 + o0, Bh0);
        cpasync16(base + 24576 + o0, Bl0);
        cpasync16(base + 16384 + o1, Bh1);
        cpasync16(base + 24576 + o1, Bl1);
        asm volatile("cp.async.commit_group;" ::: "memory");
    }

    for (int i = 0; i < NCH; ++i) {
        const bool more = (i + 1 < NCH);
        if (more) {
            const int ku = (i + 1) << 2;
            uint32_t base = sbase + ((i + 1) & 1) * 32768;
            cpasync16(base + o0, Ah0 + ku);
            cpasync16(base + 8192 + o0, Al0 + ku);
            cpasync16(base + o1, Ah1 + ku);
            cpasync16(base + 8192 + o1, Al1 + ku);
            cpasync16(base + 16384 + o0, Bh0 + ku);
            cpasync16(base + 24576 + o0, Bl0 + ku);
            cpasync16(base + 16384 + o1, Bh1 + ku);
            cpasync16(base + 24576 + o1, Bl1 + ku);
            asm volatile("cp.async.commit_group;" ::: "memory");
            asm volatile("cp.async.wait_group 1;" ::: "memory");
        } else {
            asm volatile("cp.async.wait_group 0;" ::: "memory");
        }
        __syncthreads();
        const uint32_t ab = sbase + (i & 1) * 32768;
        const uint32_t bb = ab + 16384;
#pragma unroll
        for (int ks = 0; ks < 2; ++ks) {
            const int r = lane & 15;
            const int cu = (ks << 1) + (lane >> 4);
            uint32_t ah[4][4], al[4][4], bh[2][4], bl[2][4];
#pragma unroll
            for (int mi = 0; mi < 4; ++mi) {
                uint32_t off = SWZB(wm * 64 + mi * 16 + r, cu);
                ldsm4(ah[mi], ab + off);
                ldsm4(al[mi], ab + 8192 + off);
            }
#pragma unroll
            for (int ni = 0; ni < 2; ++ni) {
                uint32_t off = SWZB(wn * 32 + ni * 16 + r, cu);
                ldsm4(bh[ni], bb + off);
                ldsm4(bl[ni], bb + 8192 + off);
            }
#pragma unroll
            for (int mi = 0; mi < 4; ++mi)
#pragma unroll
                for (int j = 0; j < 4; ++j) {
                    const int ni = j >> 1, s = j & 1;
                    mma16816(acc[mi][j], ah[mi], bh[ni][s], bh[ni][s + 2]);
                    mma16816(acc[mi][j], al[mi], bh[ni][s], bh[ni][s + 2]);
                    mma16816(acc[mi][j], ah[mi], bl[ni][s], bl[ni][s + 2]);
                }
        }
        __syncthreads();
    }

#pragma unroll
    for (int mi = 0; mi < 4; ++mi)
#pragma unroll
        for (int j = 0; j < 4; ++j) {
            const int row = m0 + wm * 64 + mi * 16 + (lane >> 2);
            const int colL = wn * 32 + j * 8 + (lane & 3) * 2;
            const float b0v = sBias[colL], b1v = sBias[colL + 1];
            float x0 = acc[mi][j][0] + b0v, x1 = acc[mi][j][1] + b1v;
            float x2 = acc[mi][j][2] + b0v, x3 = acc[mi][j][3] + b1v;
            if (RELU) {
                x0 = fmaxf(x0, 0.f); x1 = fmaxf(x1, 0.f);
                x2 = fmaxf(x2, 0.f); x3 = fmaxf(x3, 0.f);
            }
            if (OUTBF) {
                uint32_t ph, pl;
                pack2(x0, x1, ph, pl);
                *(uint32_t*)(Chi + (size_t)row * ldo + n0 + colL) = ph;
                *(uint32_t*)(Clo + (size_t)row * ldo + n0 + colL) = pl;
                pack2(x2, x3, ph, pl);
                *(uint32_t*)(Chi + (size_t)(row + 8) * ldo + n0 + colL) = ph;
                *(uint32_t*)(Clo + (size_t)(row + 8) * ldo + n0 + colL) = pl;
            } else {
                *(float2*)(Cf + (size_t)row * ldo + n0 + colL) = make_float2(x0, x1);
                *(float2*)(Cf + (size_t)(row + 8) * ldo + n0 + colL) = make_float2(x2, x3);
            }
        }
}

// ------------------------- fused deltas(2x) + feat assembly -> bf16 hi/lo -------------------------
__device__ __forceinline__ float4 d1_at(const float4* __restrict__ h4, size_t base, int t, int c4) {
    int tp1 = min(t + 1, 1023), tm1 = max(t - 1, 0);
    int tp2 = min(t + 2, 1023), tm2 = max(t - 2, 0);
    float4 a = h4[base + (size_t)tp1 * 64 + c4];
    float4 b = h4[base + (size_t)tm1 * 64 + c4];
    float4 c = h4[base + (size_t)tp2 * 64 + c4];
    float4 d = h4[base + (size_t)tm2 * 64 + c4];
    float4 z;
    z.x = (a.x - b.x) * 0.5f + (c.x - d.x) * 0.25f;
    z.y = (a.y - b.y) * 0.5f + (c.y - d.y) * 0.25f;
    z.z = (a.z - b.z) * 0.5f + (c.z - d.z) * 0.25f;
    z.w = (a.w - b.w) * 0.5f + (c.w - d.w) * 0.25f;
    return z;
}

__global__ void feat_k() {
    int idx = blockIdx.x * 256 + threadIdx.x;
    if (idx >= 32 * 1024 * 64) return;
    int c4 = idx & 63, t = (idx >> 6) & 1023, sb = idx >> 16;
    int b = d_order[sb];
    const float4* h4 = (const float4*)d_h;
    size_t base = (size_t)b * 65536;
    float4 hv = h4[base + (size_t)t * 64 + c4];
    float4 d1v = d1_at(h4, base, t, c4);
    int tp1 = min(t + 1, 1023), tm1 = max(t - 1, 0);
    int tp2 = min(t + 2, 1023), tm2 = max(t - 2, 0);
    float4 a = d1_at(h4, base, tp1, c4);
    float4 bb = d1_at(h4, base, tm1, c4);
    float4 c = d1_at(h4, base, tp2, c4);
    float4 d = d1_at(h4, base, tm2, c4);
    float4 d2v;
    d2v.x = (a.x - bb.x) * 0.5f + (c.x - d.x) * 0.25f;
    d2v.y = (a.y - bb.y) * 0.5f + (c.y - d.y) * 0.25f;
    d2v.z = (a.z - bb.z) * 0.5f + (c.z - d.z) * 0.25f;
    d2v.w = (a.w - bb.w) * 0.5f + (c.w - d.w) * 0.25f;
    uint32_t* Fh32 = (uint32_t*)d_Fh;
    uint32_t* Fl32 = (uint32_t*)d_Fl;
    size_t ob = ((size_t)sb * 1024 + t) * 384;
    uint2 hp, lp;
    pack2(hv.x, hv.y, hp.x, lp.x);
    pack2(hv.z, hv.w, hp.y, lp.y);
    *(uint2*)&Fh32[ob + c4 * 2] = hp;
    *(uint2*)&Fl32[ob + c4 * 2] = lp;
    pack2(d1v.x, d1v.y, hp.x, lp.x);
    pack2(d1v.z, d1v.w, hp.y, lp.y);
    *(uint2*)&Fh32[ob + 128 + c4 * 2] = hp;
    *(uint2*)&Fl32[ob + 128 + c4 * 2] = lp;
    pack2(d2v.x, d2v.y, hp.x, lp.x);
    pack2(d2v.z, d2v.w, hp.y, lp.y);
    *(uint2*)&Fh32[ob + 256 + c4 * 2] = hp;
    *(uint2*)&Fl32[ob + 256 + c4 * 2] = lp;
}

// ------------------------- persistent bidirectional LSTM recurrence (HMMA, fragment-direct) -------
// 128 CTAs: dir = cta>>6, slice = cta&63. Gates on 128 threads (R13 posting: tid0, 64 arrivals).
// Z staged pre-spin into double-buffered zs (static data, no ordering needed).
// smem: W-stage 16K (init only) | P 17408 | zs 2 x 8448
__global__ void __launch_bounds__(256, 1) lstm_rec_k(
    const float* __restrict__ Whh_f, const float* __restrict__ Whh_b,
    const float* __restrict__ h0, const float* __restrict__ c0) {
    extern __shared__ char smc[];
    const int POFF = 16384, ZOFF = POFF + 17408;
    float* P = (float*)(smc + POFF);
    const uint32_t sb = s2u(smc);
    const int tid = threadIdx.x, lane = tid & 31, wid = tid >> 5;
    const int dir = blockIdx.x >> 6, slice = blockIdx.x & 63;
    const float* Whh = dir ? Whh_b : Whh_f;

    // stage W slice into smem (ldsm layout), init only
    for (int i = tid; i < 4096; i += 256) {
        int r = i >> 8, k = i & 255;
        int grow = ((r >> 2) << 8) + (slice << 2) + (r & 3);
        float w = __ldg(Whh + (size_t)grow * 256 + k);
        uint32_t ph, pl;
        {
            uint32_t u = cvt2bf(0.f, w);
            float resid = w - __uint_as_float(u & 0xffff0000u);
            ph = u;
            pl = cvt2bf(0.f, resid);
        }
        int c = k >> 3;
        int phys = (c & 24) | ((c ^ r) & 7);
        int off = r * 512 + phys * 16 + (k & 7) * 2;
        *(uint16_t*)(smc + off) = (uint16_t)(ph >> 16);
        *(uint16_t*)(smc + 8192 + off) = (uint16_t)(pl >> 16);
    }
    __syncthreads();
    // B fragments into registers (loop-invariant)
    const int rr = lane & 15, hs = lane >> 4;
    uint32_t bfh[2][4], bfl[2][4];
#pragma unroll
    for (int kt = 0; kt < 2; ++kt) {
        int cu = wid * 4 + kt * 2 + hs;
        int phys = (cu & 24) | ((cu ^ rr) & 7);
        uint32_t off = (uint32_t)(rr * 512 + phys * 16);
        ldsm4(bfh[kt], sb + off);
        ldsm4(bfl[kt], sb + 8192 + off);
    }

    // gate mapping: tid<128: gb = tid>>2, gj = tid&3; k = slice*4 + gj
    const int gb = tid >> 2, gj = tid & 3;
    const int gk = (slice << 2) + gj;
    float creg = 0.f;
    int Lb = 0;
    if (tid < 128) {
        Lb = d_lens[tid & 31];
        creg = c0[(dir * 32 + gb) * 256 + gk];
        float f = h0[(dir * 32 + gb) * 256 + gk];
        float f1 = __shfl_xor_sync(0xffffffffu, f, 1);
        if ((gj & 1) == 0) write_frag(0, dir, gb, gk, f, f1);
    }
    __syncthreads();
    if (tid == 0)
        asm volatile("red.release.gpu.global.add.u32 [%0], %1;"
                     :: "l"(&d_ctr2[dir]), "r"(1u) : "memory");

    for (int t = 0; t < 1024; ++t) {
        // Z prefetch + scatter to double-buffered zs BEFORE the spin (d_Z is static)
        float* zs = (float*)(smc + ZOFF + (t & 1) * 8448);
        int zg = tid >> 5, zb = tid & 31;
        if (tid < 128) {
            int tt = dir ? max(Lb - 1 - t, 0) : t;
            const float* zp = d_Z + ((size_t)zb * 1024 + tt) * 2048 + dir * 1024 + (slice << 2) + (zg << 8);
            float4 zv = *(const float4*)zp;
            zs[(0 * 4 + zg) * 33 + zb] = zv.x;
            zs[(1 * 4 + zg) * 33 + zb] = zv.y;
            zs[(2 * 4 + zg) * 33 + zb] = zv.z;
            zs[(3 * 4 + zg) * 33 + zb] = zv.w;
        }
        if (tid == 0) {
            unsigned tgt = 64u * (unsigned)(t + 1), v;
            do {
                asm volatile("ld.acquire.gpu.global.u32 %0, [%1];"
                             : "=r"(v) : "l"(&d_ctr2[dir]) : "memory");
            } while (v < tgt);
        }
        __syncthreads();
        uint32_t ahr[2][2][4], alr[2][2][4];
        {
            const uint4* hf = &d_Hfrag[t & 1][dir][0];
#pragma unroll
            for (int mt = 0; mt < 2; ++mt)
#pragma unroll
                for (int kt = 0; kt < 2; ++kt) {
                    int u4 = (((wid * 2 + mt) * 2 + kt) * 2) * 32 + lane;
                    uint4 v = __ldcg(hf + u4);
                    ahr[mt][kt][0] = v.x; ahr[mt][kt][1] = v.y;
                    ahr[mt][kt][2] = v.z; ahr[mt][kt][3] = v.w;
                    v = __ldcg(hf + u4 + 32);
                    alr[mt][kt][0] = v.x; alr[mt][kt][1] = v.y;
                    alr[mt][kt][2] = v.z; alr[mt][kt][3] = v.w;
                }
        }
        float acc[2][2][4];
#pragma unroll
        for (int a = 0; a < 2; a++)
#pragma unroll
            for (int bq = 0; bq < 2; bq++)
#pragma unroll
                for (int q2 = 0; q2 < 4; q2++) acc[a][bq][q2] = 0.f;
#pragma unroll
        for (int mt = 0; mt < 2; ++mt)
#pragma unroll
            for (int nt = 0; nt < 2; ++nt)
#pragma unroll
                for (int kt = 0; kt < 2; ++kt) {
                    mma16816(acc[mt][nt], ahr[mt][kt], bfh[kt][nt], bfh[kt][nt + 2]);
                    mma16816(acc[mt][nt], alr[mt][kt], bfh[kt][nt], bfh[kt][nt + 2]);
                    mma16816(acc[mt][nt], ahr[mt][kt], bfl[kt][nt], bfl[kt][nt + 2]);
                }
#pragma unroll
        for (int mt = 0; mt < 2; ++mt)
#pragma unroll
            for (int nt = 0; nt < 2; ++nt) {
                int b = mt * 16 + (lane >> 2);
                int r = nt * 8 + (lane & 3) * 2;
                P[(wid * 32 + b) * 17 + r] = acc[mt][nt][0];
                P[(wid * 32 + b) * 17 + r + 1] = acc[mt][nt][1];
                P[(wid * 32 + b + 8) * 17 + r] = acc[mt][nt][2];
                P[(wid * 32 + b + 8) * 17 + r + 1] = acc[mt][nt][3];
            }
        __syncthreads();
        float hv = 0.f;
        if (tid < 128) {
            float g4[4];
#pragma unroll
            for (int g = 0; g < 4; ++g) {
                float s = zs[(gj * 4 + g) * 33 + gb];
                int ri = 4 * g + gj;
#pragma unroll
                for (int w8 = 0; w8 < 8; ++w8) s += P[(w8 * 32 + gb) * 17 + ri];
                g4[g] = s;
            }
            float is = 1.f / (1.f + expf(-g4[0]));
            float fs = 1.f / (1.f + expf(-g4[1]));
            float gt = tanhf(g4[2]);
            float os = 1.f / (1.f + expf(-g4[3]));
            creg = fs * creg + is * gt;
            hv = os * tanhf(creg);
            float hv1 = __shfl_xor_sync(0xffffffffu, hv, 1);
            if ((gj & 1) == 0) write_frag((t + 1) & 1, dir, gb, gk, hv, hv1);
        }
        __syncthreads();
        if (tid == 0)
            asm volatile("red.release.gpu.global.add.u32 [%0], %1;"
                         :: "l"(&d_ctr2[dir]), "r"(1u) : "memory");
        // Hout store off the critical path (overlaps next step's spin)
        if (tid < 128) d_Hout[dir][t][gk][gb] = hv;
    }
}

// ------------------------- output assembly (smem-tiled transpose) -------------------------
__global__ void __launch_bounds__(256) outk(float* __restrict__ out) {
    __shared__ float sm[256][33];
    const int tid = threadIdx.x, lane = tid & 31, wid = tid >> 5;
    const int bid = blockIdx.x;
    if (bid < 1024) {
        const int t = bid;
        const float* src = &d_Hout[0][t][0][0];
#pragma unroll 4
        for (int q = 0; q < 32; ++q) {
            int j = wid + 8 * q;
            sm[j][lane] = src[j * 32 + lane];
        }
        __syncthreads();
        for (int sq = 0; sq < 4; ++sq) {
            int sbv = wid * 4 + sq;
            int L = d_lens[sbv];
            float* dst = out + ((size_t)sbv * 1024 + t) * 512;
            if (t < L) {
#pragma unroll
                for (int q = 0; q < 8; ++q) dst[q * 32 + lane] = sm[q * 32 + lane][sbv];
            } else {
#pragma unroll
                for (int q = 0; q < 16; ++q) dst[q * 32 + lane] = 0.f;
            }
        }
    } else {
        const int s = bid - 1024;
        const float* src = &d_Hout[1][s][0][0];
#pragma unroll 4
        for (int q = 0; q < 32; ++q) {
            int j = wid + 8 * q;
            sm[j][lane] = src[j * 32 + lane];
        }
        __syncthreads();
        for (int sq = 0; sq < 4; ++sq) {
            int sbv = wid * 4 + sq;
            int L = d_lens[sbv];
            if (s < L) {
                int t = L - 1 - s;
                float* dst = out + ((size_t)sbv * 1024 + t) * 512 + 256;
#pragma unroll
                for (int q = 0; q < 8; ++q) dst[q * 32 + lane] = sm[q * 32 + lane][sbv];
            }
        }
    }
}

__global__ void tailk(float* __restrict__ out, int out_size) {
    int k = threadIdx.x;
    int idx = 16777216 + k;
    if (idx >= out_size) return;
    for (; idx < out_size; idx += 256, k += 256)
        out[idx] = (k < 32) ? (float)d_order[k] : 0.f;
}

// ------------------------- launch -------------------------
extern "C" void kernel_launch(void* const* d_in, const int* in_sizes, int n_in,
                              void* d_out, int out_size) {
    const float* x = (const float*)d_in[0];
    const int* xlen = (const int*)d_in[1];
    const float* W0 = (const float*)d_in[2];
    const float* b0 = (const float*)d_in[3];
    const float* W1 = (const float*)d_in[4];
    const float* b1 = (const float*)d_in[5];
    const float* W2 = (const float*)d_in[6];
    const float* b2 = (const float*)d_in[7];
    const float* Wih_f = (const float*)d_in[8];
    const float* Whh_f = (const float*)d_in[9];
    const float* bih_f = (const float*)d_in[10];
    const float* bhh_f = (const float*)d_in[11];
    const float* Wih_b = (const float*)d_in[12];
    const float* Whh_b = (const float*)d_in[13];
    const float* bih_b = (const float*)d_in[14];
    const float* bhh_b = (const float*)d_in[15];
    const float* h0 = (const float*)d_in[16];
    const float* c0 = (const float*)d_in[17];
    float* out = (float*)d_out;

    void *p_xh, *p_xl, *p_w0h, *p_w0l, *p_w1h, *p_w1l, *p_w2h, *p_w2l;
    void *p_wch, *p_wcl, *p_h, *p_Z, *p_bias;
    void *p_a0h, *p_a0l, *p_a1h, *p_a1l, *p_fh, *p_fl;
    cudaGetSymbolAddress(&p_h, d_h);
    cudaGetSymbolAddress(&p_Z, d_Z);
    cudaGetSymbolAddress(&p_bias, d_biascat);
    cudaGetSymbolAddress(&p_wch, d_Wch);
    cudaGetSymbolAddress(&p_wcl, d_Wcl);
    cudaGetSymbolAddress(&p_w1h, d_W1h);
    cudaGetSymbolAddress(&p_w1l, d_W1l);
    cudaGetSymbolAddress(&p_w2h, d_W2h);
    cudaGetSymbolAddress(&p_w2l, d_W2l);
    cudaGetSymbolAddress(&p_w0h, d_W0h);
    cudaGetSymbolAddress(&p_w0l, d_W0l);
    cudaGetSymbolAddress(&p_xh, d_Xh);
    cudaGetSymbolAddress(&p_xl, d_Xl);
    cudaGetSymbolAddress(&p_a0h, d_A0h);
    cudaGetSymbolAddress(&p_a0l, d_A0l);
    cudaGetSymbolAddress(&p_a1h, d_A1h);
    cudaGetSymbolAddress(&p_a1l, d_A1l);
    cudaGetSymbolAddress(&p_fh, d_Fh);
    cudaGetSymbolAddress(&p_fl, d_Fl);

    cudaFuncSetAttribute(gemm_mma_k<0, 0>, cudaFuncAttributeMaxDynamicSharedMemorySize, 66048);
    cudaFuncSetAttribute(gemm_mma_k<1, 0>, cudaFuncAttributeMaxDynamicSharedMemorySize, 66048);
    cudaFuncSetAttribute(gemm_mma_k<1, 1>, cudaFuncAttributeMaxDynamicSharedMemorySize, 66048);
    cudaFuncSetAttribute(lstm_rec_k, cudaFuncAttributeMaxDynamicSharedMemorySize, 51000);

    prep_k<<<512, 256>>>(x, xlen, W0, W1, W2, Wih_f, Wih_b, bih_f, bhh_f, bih_b, bhh_b);
    gemm_mma_k<1, 1><<<dim3(4, 256), 256, 66048>>>(
        (const uint16_t*)p_xh, (const uint16_t*)p_xl,
        (const uint16_t*)p_w0h, (const uint16_t*)p_w0l,
        b0, nullptr, (uint16_t*)p_a0h, (uint16_t*)p_a0l, 96, 512);
    gemm_mma_k<1, 1><<<dim3(4, 256), 256, 66048>>>(
        (const uint16_t*)p_a0h, (const uint16_t*)p_a0l,
        (const uint16_t*)p_w1h, (const uint16_t*)p_w1l,
        b1, nullptr, (uint16_t*)p_a1h, (uint16_t*)p_a1l, 512, 512);
    gemm_mma_k<1, 0><<<dim3(2, 256), 256, 66048>>>(
        (const uint16_t*)p_a1h, (const uint16_t*)p_a1l,
        (const uint16_t*)p_w2h, (const uint16_t*)p_w2l,
        b2, (float*)p_h, nullptr, nullptr, 512, 256);
    feat_k<<<8192, 256>>>();
    gemm_mma_k<0, 0><<<dim3(16, 256), 256, 66048>>>(
        (const uint16_t*)p_fh, (const uint16_t*)p_fl,
        (const uint16_t*)p_wch, (const uint16_t*)p_wcl,
        (const float*)p_bias, (float*)p_Z, nullptr, nullptr, 768, 2048);
    lstm_rec_k<<<128, 256, 51000>>>(Whh_f, Whh_b, h0, c0);
    outk<<<2048, 256>>>(out);
    tailk<<<1, 256>>>(out, out_size);
}

// round 16
// speedup vs baseline: 1.0736x; 1.0736x over previous
#include <cuda_runtime.h>
#include <math.h>
#include <stdint.h>
#include <string.h>

// B=32, T=1024, D_IN=80, enc: 80->512->512->256 (ReLU), F=768, 4H=1024, H=256

// ------------------------- device scratch -------------------------
__device__ float d_h[32768 * 256];
__device__ float d_Z[32768 * 2048];        // [b][t][2048]: cols 0..1023 fwd, 1024..2047 bwd
__device__ float d_biascat[2048];
__device__ uint4 d_Hfrag[2][2][2048];      // [parity][dir][(((wid*2+mt)*2+kt)*2+hl)*32+lane]
__device__ float d_Hout[2][1024][256][32]; // [dir][t][k][b]
__device__ int d_order[32];
__device__ int d_lens[32];
__device__ unsigned d_ctr2[2];
// pre-converted bf16 hi/lo weights + activations
__device__ uint16_t d_Wch[2048 * 768], d_Wcl[2048 * 768];
__device__ uint16_t d_W1h[512 * 512], d_W1l[512 * 512];
__device__ uint16_t d_W2h[256 * 512], d_W2l[256 * 512];
__device__ uint16_t d_W0h[512 * 96], d_W0l[512 * 96];
__device__ uint16_t d_Xh[32768 * 96], d_Xl[32768 * 96];
__device__ uint16_t d_A0h[32768 * 512], d_A0l[32768 * 512];
__device__ uint16_t d_A1h[32768 * 512], d_A1l[32768 * 512];
__device__ uint16_t d_Fh[32768 * 768], d_Fl[32768 * 768];

// ------------------------- helpers -------------------------
__device__ __forceinline__ uint32_t s2u(const void* p) {
    uint32_t a;
    asm("{ .reg .u64 t; cvta.to.shared.u64 t, %1; cvt.u32.u64 %0, t; }" : "=r"(a) : "l"(p));
    return a;
}
__device__ __forceinline__ uint32_t cvt2bf(float lo, float hi) {
    uint32_t r;
    asm("cvt.rn.satfinite.bf16x2.f32 %0, %1, %2;" : "=r"(r) : "f"(hi), "f"(lo));
    return r;
}
__device__ __forceinline__ void pack2(float x0, float x1, uint32_t& ph, uint32_t& pl) {
    ph = cvt2bf(x0, x1);
    float r0 = x0 - __uint_as_float(ph << 16);
    float r1 = x1 - __uint_as_float(ph & 0xffff0000u);
    pl = cvt2bf(r0, r1);
}
__device__ __forceinline__ void ldsm4(uint32_t* r, uint32_t addr) {
    asm volatile("ldmatrix.sync.aligned.m8n8.x4.shared.b16 {%0,%1,%2,%3}, [%4];"
                 : "=r"(r[0]), "=r"(r[1]), "=r"(r[2]), "=r"(r[3]) : "r"(addr));
}
__device__ __forceinline__ void mma16816(float* c, const uint32_t* a, uint32_t b0, uint32_t b1) {
    asm volatile(
        "mma.sync.aligned.m16n8k16.row.col.f32.bf16.bf16.f32 "
        "{%0,%1,%2,%3}, {%4,%5,%6,%7}, {%8,%9}, {%0,%1,%2,%3};"
        : "+f"(c[0]), "+f"(c[1]), "+f"(c[2]), "+f"(c[3])
        : "r"(a[0]), "r"(a[1]), "r"(a[2]), "r"(a[3]), "r"(b0), "r"(b1));
}
__device__ __forceinline__ void cpasync16(uint32_t smem_dst, const void* gsrc) {
    asm volatile("cp.async.cg.shared.global [%0], [%1], 16;"
                 :: "r"(smem_dst), "l"(gsrc) : "memory");
}
#define SWZB(row, c) ((((uint32_t)(row)) << 6) + ((((uint32_t)(c) ^ (((uint32_t)(row) >> 1) & 3))) << 4))

// write (f0,f1) for (b, k0, k0+1) as mma A-fragment (hi + lo residual)
__device__ __forceinline__ void write_frag(int parity, int dir, int b, int k0, float f0, float f1) {
    uint32_t hi = cvt2bf(f0, f1);
    float r0 = f0 - __uint_as_float(hi << 16);
    float r1 = f1 - __uint_as_float(hi & 0xffff0000u);
    uint32_t lo = cvt2bf(r0, r1);
    int wd = k0 >> 5, kt = (k0 >> 4) & 1, jhi = (k0 >> 3) & 1, ll = (k0 >> 1) & 3;
    int mt = b >> 4, jlo = (b >> 3) & 1, L = (b & 7) * 4 + ll, j = jhi * 2 + jlo;
    uint32_t* H = (uint32_t*)&d_Hfrag[parity][dir][0];
    int base = ((wd * 2 + mt) * 2 + kt) * 2;
    H[(size_t)(((base + 0) * 32 + L) * 4 + j)] = hi;
    H[(size_t)(((base + 1) * 32 + L) * 4 + j)] = lo;
}

__device__ __forceinline__ void conv_range(const float* __restrict__ src,
                                           uint16_t* __restrict__ dh, uint16_t* __restrict__ dl,
                                           int npairs, int tid, int nth) {
    for (int i = tid; i < npairs; i += nth) {
        float2 v = ((const float2*)src)[i];
        uint32_t ph, pl;
        pack2(v.x, v.y, ph, pl);
        ((uint32_t*)dh)[i] = ph;
        ((uint32_t*)dl)[i] = pl;
    }
}

__device__ __forceinline__ void conv_pad(const float* __restrict__ src,
                                         uint16_t* __restrict__ dh, uint16_t* __restrict__ dl,
                                         int rows, int kreal, int kpad2, int tid, int nth) {
    const int rp = kreal >> 1;
    for (int i = tid; i < rows * kpad2; i += nth) {
        int row = i / kpad2, cp = i % kpad2;
        uint32_t ph = 0, pl = 0;
        if (cp < rp) {
            float2 v = *(const float2*)(src + (size_t)row * kreal + cp * 2);
            pack2(v.x, v.y, ph, pl);
        }
        ((uint32_t*)dh)[i] = ph;
        ((uint32_t*)dl)[i] = pl;
    }
}

// ------------------------- prep: order, biascat, all conversions -------------------------
__global__ void __launch_bounds__(256) prep_k(
    const float* __restrict__ x, const int* __restrict__ xlen,
    const float* __restrict__ W0, const float* __restrict__ W1, const float* __restrict__ W2,
    const float* __restrict__ Wihf, const float* __restrict__ Wihb,
    const float* __restrict__ bihf, const float* __restrict__ bhhf,
    const float* __restrict__ bihb, const float* __restrict__ bhhb) {
    const int ptid = blockIdx.x * 256 + threadIdx.x;
    const int nth = gridDim.x * 256;
    if (ptid == 0) {
        unsigned used = 0;
        for (int p = 0; p < 32; ++p) {
            int best = -1, bl = -2147483647;
            for (int j = 0; j < 32; ++j) {
                if (used & (1u << j)) continue;
                int L = xlen[j];
                if (L > bl) { bl = L; best = j; }
            }
            used |= (1u << best);
            d_order[p] = best;
            d_lens[p] = bl;
        }
        d_ctr2[0] = 0u;
        d_ctr2[1] = 0u;
    }
    if (ptid < 1024) d_biascat[ptid] = bihf[ptid] + bhhf[ptid];
    else if (ptid < 2048) d_biascat[ptid] = bihb[ptid - 1024] + bhhb[ptid - 1024];
    conv_pad(x, d_Xh, d_Xl, 32768, 80, 48, ptid, nth);
    conv_pad(W0, d_W0h, d_W0l, 512, 80, 48, ptid, nth);
    conv_range(W1, d_W1h, d_W1l, 131072, ptid, nth);
    conv_range(W2, d_W2h, d_W2l, 65536, ptid, nth);
    conv_range(Wihf, d_Wch, d_Wcl, 393216, ptid, nth);
    conv_range(Wihb, d_Wch + 1024 * 768, d_Wcl + 1024 * 768, 393216, ptid, nth);
}

// ------------------------- HMMA split-bf16 GEMM (3-stage cp.async, 2 CTAs/SM) ------------------
// smem: 3 x 32KB chunk bufs + bias  -> 98816 B
template <int RELU, int OUTBF>
__global__ void __launch_bounds__(256, 2) gemm_mma_k(
    const uint16_t* __restrict__ Ahi, const uint16_t* __restrict__ Alo,
    const uint16_t* __restrict__ Bhi, const uint16_t* __restrict__ Blo,
    const float* __restrict__ bias, float* __restrict__ Cf,
    uint16_t* __restrict__ Chi, uint16_t* __restrict__ Clo,
    int K, int ldo) {
    extern __shared__ char smc[];
    const int tid = threadIdx.x, lane = tid & 31, wid = tid >> 5;
    const int wm = wid >> 2, wn = wid & 3;
    const int n0 = blockIdx.x * 128, m0 = blockIdx.y * 128;
    const int NCH = K >> 5;
    const uint32_t sbase = s2u(smc);
    float* sBias = (float*)(smc + 98304);
    if (tid < 128) sBias[tid] = bias[n0 + tid];

    const int ra = tid >> 2, ca = tid & 3;
    const int ldu = K >> 3;
    const uint4* Ah0 = (const uint4*)Ahi + (size_t)(m0 + ra) * ldu + ca;
    const uint4* Al0 = (const uint4*)Alo + (size_t)(m0 + ra) * ldu + ca;
    const uint4* Ah1 = (const uint4*)Ahi + (size_t)(m0 + 64 + ra) * ldu + ca;
    const uint4* Al1 = (const uint4*)Alo + (size_t)(m0 + 64 + ra) * ldu + ca;
    const uint4* Bh0 = (const uint4*)Bhi + (size_t)(n0 + ra) * ldu + ca;
    const uint4* Bl0 = (const uint4*)Blo + (size_t)(n0 + ra) * ldu + ca;
    const uint4* Bh1 = (const uint4*)Bhi + (size_t)(n0 + 64 + ra) * ldu + ca;
    const uint4* Bl1 = (const uint4*)Blo + (size_t)(n0 + 64 + ra) * ldu + ca;

    float acc[4][4][4];
#pragma unroll
    for (int mi = 0; mi < 4; mi++)
#pragma unroll
        for (int j = 0; j < 4; j++)
#pragma unroll
            for (int q = 0; q < 4; q++) acc[mi][j][q] = 0.f;

    const uint32_t o0 = SWZB(ra, ca), o1 = SWZB(64 + ra, ca);
#define ISSUE_CHUNK(ci, bufi)                                     \
    do {                                                          \
        const int ku_ = (ci) << 2;                                \
        uint32_t base_ = sbase + (bufi) * 32768;                  \
        cpasync16(base_ + o0, Ah0 + ku_);                         \
        cpasync16(base_ + 8192 + o0, Al0 + ku_);                  \
        cpasync16(base_ + o1, Ah1 + ku_);                         \
        cpasync16(base_ + 8192 + o1, Al1 + ku_);                  \
        cpasync16(base_ + 16384 + o0, Bh0 + ku_);                 \
        cpasync16(base_ + 24576 + o0, Bl0 + ku_);                 \
        cpasync16(base_ + 16384 + o1, Bh1 + ku_);                 \
        cpasync16(base_ + 24576 + o1, Bl1 + ku_);                 \
        asm volatile("cp.async.commit_group;" ::: "memory");      \
    } while (0)

    // prologue: chunks 0 and 1 into bufs 0 and 1
    ISSUE_CHUNK(0, 0);
    if (NCH > 1) ISSUE_CHUNK(1, 1);

    int buf = 0;
    for (int i = 0; i < NCH; ++i) {
        // protect buf[(i+2)%3] (read during iter i-1) before overwriting
        __syncthreads();
        if (i + 2 < NCH) {
            int b2 = buf + 2;
            if (b2 >= 3) b2 -= 3;
            ISSUE_CHUNK(i + 2, b2);
            asm volatile("cp.async.wait_group 2;" ::: "memory");
        } else if (i + 1 < NCH) {
            asm volatile("cp.async.wait_group 1;" ::: "memory");
        } else {
            asm volatile("cp.async.wait_group 0;" ::: "memory");
        }
        __syncthreads();
        const uint32_t ab = sbase + buf * 32768;
        const uint32_t bb = ab + 16384;
#pragma unroll
        for (int ks = 0; ks < 2; ++ks) {
            const int r = lane & 15;
            const int cu = (ks << 1) + (lane >> 4);
            uint32_t ah[4][4], al[4][4], bh[2][4], bl[2][4];
#pragma unroll
            for (int mi = 0; mi < 4; ++mi) {
                uint32_t off = SWZB(wm * 64 + mi * 16 + r, cu);
                ldsm4(ah[mi], ab + off);
                ldsm4(al[mi], ab + 8192 + off);
            }
#pragma unroll
            for (int ni = 0; ni < 2; ++ni) {
                uint32_t off = SWZB(wn * 32 + ni * 16 + r, cu);
                ldsm4(bh[ni], bb + off);
                ldsm4(bl[ni], bb + 8192 + off);
            }
#pragma unroll
            for (int mi = 0; mi < 4; ++mi)
#pragma unroll
                for (int j = 0; j < 4; ++j) {
                    const int ni = j >> 1, s = j & 1;
                    mma16816(acc[mi][j], ah[mi], bh[ni][s], bh[ni][s + 2]);
                    mma16816(acc[mi][j], al[mi], bh[ni][s], bh[ni][s + 2]);
                    mma16816(acc[mi][j], ah[mi], bl[ni][s], bl[ni][s + 2]);
                }
        }
        if (++buf == 3) buf = 0;
    }
#undef ISSUE_CHUNK

#pragma unroll
    for (int mi = 0; mi < 4; ++mi)
#pragma unroll
        for (int j = 0; j < 4; ++j) {
            const int row = m0 + wm * 64 + mi * 16 + (lane >> 2);
            const int colL = wn * 32 + j * 8 + (lane & 3) * 2;
            const float b0v = sBias[colL], b1v = sBias[colL + 1];
            float x0 = acc[mi][j][0] + b0v, x1 = acc[mi][j][1] + b1v;
            float x2 = acc[mi][j][2] + b0v, x3 = acc[mi][j][3] + b1v;
            if (RELU) {
                x0 = fmaxf(x0, 0.f); x1 = fmaxf(x1, 0.f);
                x2 = fmaxf(x2, 0.f); x3 = fmaxf(x3, 0.f);
            }
            if (OUTBF) {
                uint32_t ph, pl;
                pack2(x0, x1, ph, pl);
                *(uint32_t*)(Chi + (size_t)row * ldo + n0 + colL) = ph;
                *(uint32_t*)(Clo + (size_t)row * ldo + n0 + colL) = pl;
                pack2(x2, x3, ph, pl);
                *(uint32_t*)(Chi + (size_t)(row + 8) * ldo + n0 + colL) = ph;
                *(uint32_t*)(Clo + (size_t)(row + 8) * ldo + n0 + colL) = pl;
            } else {
                *(float2*)(Cf + (size_t)row * ldo + n0 + colL) = make_float2(x0, x1);
                *(float2*)(Cf + (size_t)(row + 8) * ldo + n0 + colL) = make_float2(x2, x3);
            }
        }
}

// ------------------------- fused deltas(2x) + feat assembly -> bf16 hi/lo -------------------------
__device__ __forceinline__ float4 d1_at(const float4* __restrict__ h4, size_t base, int t, int c4) {
    int tp1 = min(t + 1, 1023), tm1 = max(t - 1, 0);
    int tp2 = min(t + 2, 1023), tm2 = max(t - 2, 0);
    float4 a = h4[base + (size_t)tp1 * 64 + c4];
    float4 b = h4[base + (size_t)tm1 * 64 + c4];
    float4 c = h4[base + (size_t)tp2 * 64 + c4];
    float4 d = h4[base + (size_t)tm2 * 64 + c4];
    float4 z;
    z.x = (a.x - b.x) * 0.5f + (c.x - d.x) * 0.25f;
    z.y = (a.y - b.y) * 0.5f + (c.y - d.y) * 0.25f;
    z.z = (a.z - b.z) * 0.5f + (c.z - d.z) * 0.25f;
    z.w = (a.w - b.w) * 0.5f + (c.w - d.w) * 0.25f;
    return z;
}

__global__ void feat_k() {
    int idx = blockIdx.x * 256 + threadIdx.x;
    if (idx >= 32 * 1024 * 64) return;
    int c4 = idx & 63, t = (idx >> 6) & 1023, sb = idx >> 16;
    int b = d_order[sb];
    const float4* h4 = (const float4*)d_h;
    size_t base = (size_t)b * 65536;
    float4 hv = h4[base + (size_t)t * 64 + c4];
    float4 d1v = d1_at(h4, base, t, c4);
    int tp1 = min(t + 1, 1023), tm1 = max(t - 1, 0);
    int tp2 = min(t + 2, 1023), tm2 = max(t - 2, 0);
    float4 a = d1_at(h4, base, tp1, c4);
    float4 bb = d1_at(h4, base, tm1, c4);
    float4 c = d1_at(h4, base, tp2, c4);
    float4 d = d1_at(h4, base, tm2, c4);
    float4 d2v;
    d2v.x = (a.x - bb.x) * 0.5f + (c.x - d.x) * 0.25f;
    d2v.y = (a.y - bb.y) * 0.5f + (c.y - d.y) * 0.25f;
    d2v.z = (a.z - bb.z) * 0.5f + (c.z - d.z) * 0.25f;
    d2v.w = (a.w - bb.w) * 0.5f + (c.w - d.w) * 0.25f;
    uint32_t* Fh32 = (uint32_t*)d_Fh;
    uint32_t* Fl32 = (uint32_t*)d_Fl;
    size_t ob = ((size_t)sb * 1024 + t) * 384;
    uint2 hp, lp;
    pack2(hv.x, hv.y, hp.x, lp.x);
    pack2(hv.z, hv.w, hp.y, lp.y);
    *(uint2*)&Fh32[ob + c4 * 2] = hp;
    *(uint2*)&Fl32[ob + c4 * 2] = lp;
    pack2(d1v.x, d1v.y, hp.x, lp.x);
    pack2(d1v.z, d1v.w, hp.y, lp.y);
    *(uint2*)&Fh32[ob + 128 + c4 * 2] = hp;
    *(uint2*)&Fl32[ob + 128 + c4 * 2] = lp;
    pack2(d2v.x, d2v.y, hp.x, lp.x);
    pack2(d2v.z, d2v.w, hp.y, lp.y);
    *(uint2*)&Fh32[ob + 256 + c4 * 2] = hp;
    *(uint2*)&Fl32[ob + 256 + c4 * 2] = lp;
}

// ------------------------- persistent bidirectional LSTM recurrence (R13 exact) -------------------
// 128 CTAs: dir = cta>>6, slice = cta&63. Gates on 128 threads; tid0 post (64 arrivals/step);
// Z loaded pre-spin (latency drains during spin), scattered post-barrier.
// smem: W-stage 16K (init only) | P 17408 | zs 2112
__global__ void __launch_bounds__(256, 1) lstm_rec_k(
    const float* __restrict__ Whh_f, const float* __restrict__ Whh_b,
    const float* __restrict__ h0, const float* __restrict__ c0) {
    extern __shared__ char smc[];
    const int POFF = 16384, ZOFF = POFF + 17408;
    float* P = (float*)(smc + POFF);
    float* zs = (float*)(smc + ZOFF);
    const uint32_t sb = s2u(smc);
    const int tid = threadIdx.x, lane = tid & 31, wid = tid >> 5;
    const int dir = blockIdx.x >> 6, slice = blockIdx.x & 63;
    const float* Whh = dir ? Whh_b : Whh_f;

    // stage W slice into smem (ldsm layout), init only
    for (int i = tid; i < 4096; i += 256) {
        int r = i >> 8, k = i & 255;
        int grow = ((r >> 2) << 8) + (slice << 2) + (r & 3);
        float w = __ldg(Whh + (size_t)grow * 256 + k);
        uint32_t ph, pl;
        {
            uint32_t u = cvt2bf(0.f, w);
            float resid = w - __uint_as_float(u & 0xffff0000u);
            ph = u;
            pl = cvt2bf(0.f, resid);
        }
        int c = k >> 3;
        int phys = (c & 24) | ((c ^ r) & 7);
        int off = r * 512 + phys * 16 + (k & 7) * 2;
        *(uint16_t*)(smc + off) = (uint16_t)(ph >> 16);
        *(uint16_t*)(smc + 8192 + off) = (uint16_t)(pl >> 16);
    }
    __syncthreads();
    // B fragments into registers (loop-invariant)
    const int rr = lane & 15, hs = lane >> 4;
    uint32_t bfh[2][4], bfl[2][4];
#pragma unroll
    for (int kt = 0; kt < 2; ++kt) {
        int cu = wid * 4 + kt * 2 + hs;
        int phys = (cu & 24) | ((cu ^ rr) & 7);
        uint32_t off = (uint32_t)(rr * 512 + phys * 16);
        ldsm4(bfh[kt], sb + off);
        ldsm4(bfl[kt], sb + 8192 + off);
    }

    // gate mapping: tid<128: gb = tid>>2, gj = tid&3; k = slice*4 + gj
    const int gb = tid >> 2, gj = tid & 3;
    const int gk = (slice << 2) + gj;
    float creg = 0.f;
    int Lb = 0;
    if (tid < 128) {
        Lb = d_lens[tid & 31];
        creg = c0[(dir * 32 + gb) * 256 + gk];
        float f = h0[(dir * 32 + gb) * 256 + gk];
        float f1 = __shfl_xor_sync(0xffffffffu, f, 1);
        if ((gj & 1) == 0) write_frag(0, dir, gb, gk, f, f1);
    }
    __syncthreads();
    if (tid == 0)
        asm volatile("red.release.gpu.global.add.u32 [%0], %1;"
                     :: "l"(&d_ctr2[dir]), "r"(1u) : "memory");

    for (int t = 0; t < 1024; ++t) {
        // Z prefetch (float4 of 4 adjacent j): latency hides under spin
        float4 zv;
        int zg = tid >> 5, zb = tid & 31;
        if (tid < 128) {
            int tt = dir ? max(Lb - 1 - t, 0) : t;
            const float* zp = d_Z + ((size_t)zb * 1024 + tt) * 2048 + dir * 1024 + (slice << 2) + (zg << 8);
            zv = *(const float4*)zp;
        }
        if (tid == 0) {
            unsigned tgt = 64u * (unsigned)(t + 1), v;
            do {
                asm volatile("ld.acquire.gpu.global.u32 %0, [%1];"
                             : "=r"(v) : "l"(&d_ctr2[dir]) : "memory");
            } while (v < tgt);
        }
        __syncthreads();
        if (tid < 128) {
            zs[(0 * 4 + zg) * 33 + zb] = zv.x;
            zs[(1 * 4 + zg) * 33 + zb] = zv.y;
            zs[(2 * 4 + zg) * 33 + zb] = zv.z;
            zs[(3 * 4 + zg) * 33 + zb] = zv.w;
        }
        uint32_t ahr[2][2][4], alr[2][2][4];
        {
            const uint4* hf = &d_Hfrag[t & 1][dir][0];
#pragma unroll
            for (int mt = 0; mt < 2; ++mt)
#pragma unroll
                for (int kt = 0; kt < 2; ++kt) {
                    int u4 = (((wid * 2 + mt) * 2 + kt) * 2) * 32 + lane;
                    uint4 v = __ldcg(hf + u4);
                    ahr[mt][kt][0] = v.x; ahr[mt][kt][1] = v.y;
                    ahr[mt][kt][2] = v.z; ahr[mt][kt][3] = v.w;
                    v = __ldcg(hf + u4 + 32);
                    alr[mt][kt][0] = v.x; alr[mt][kt][1] = v.y;
                    alr[mt][kt][2] = v.z; alr[mt][kt][3] = v.w;
                }
        }
        float acc[2][2][4];
#pragma unroll
        for (int a = 0; a < 2; a++)
#pragma unroll
            for (int bq = 0; bq < 2; bq++)
#pragma unroll
                for (int q2 = 0; q2 < 4; q2++) acc[a][bq][q2] = 0.f;
#pragma unroll
        for (int mt = 0; mt < 2; ++mt)
#pragma unroll
            for (int nt = 0; nt < 2; ++nt)
#pragma unroll
                for (int kt = 0; kt < 2; ++kt) {
                    mma16816(acc[mt][nt], ahr[mt][kt], bfh[kt][nt], bfh[kt][nt + 2]);
                    mma16816(acc[mt][nt], alr[mt][kt], bfh[kt][nt], bfh[kt][nt + 2]);
                    mma16816(acc[mt][nt], ahr[mt][kt], bfl[kt][nt], bfl[kt][nt + 2]);
                }
#pragma unroll
        for (int mt = 0; mt < 2; ++mt)
#pragma unroll
            for (int nt = 0; nt < 2; ++nt) {
                int b = mt * 16 + (lane >> 2);
                int r = nt * 8 + (lane & 3) * 2;
                P[(wid * 32 + b) * 17 + r] = acc[mt][nt][0];
                P[(wid * 32 + b) * 17 + r + 1] = acc[mt][nt][1];
                P[(wid * 32 + b + 8) * 17 + r] = acc[mt][nt][2];
                P[(wid * 32 + b + 8) * 17 + r + 1] = acc[mt][nt][3];
            }
        __syncthreads();
        float hv = 0.f;
        if (tid < 128) {
            float g4[4];
#pragma unroll
            for (int g = 0; g < 4; ++g) {
                float s = zs[(gj * 4 + g) * 33 + gb];
                int ri = 4 * g + gj;
#pragma unroll
                for (int w8 = 0; w8 < 8; ++w8) s += P[(w8 * 32 + gb) * 17 + ri];
                g4[g] = s;
            }
            float is = 1.f / (1.f + expf(-g4[0]));
            float fs = 1.f / (1.f + expf(-g4[1]));
            float gt = tanhf(g4[2]);
            float os = 1.f / (1.f + expf(-g4[3]));
            creg = fs * creg + is * gt;
            hv = os * tanhf(creg);
            float hv1 = __shfl_xor_sync(0xffffffffu, hv, 1);
            if ((gj & 1) == 0) write_frag((t + 1) & 1, dir, gb, gk, hv, hv1);
        }
        __syncthreads();
        if (tid == 0)
            asm volatile("red.release.gpu.global.add.u32 [%0], %1;"
                         :: "l"(&d_ctr2[dir]), "r"(1u) : "memory");
        // Hout store off the critical path (overlaps next step's spin)
        if (tid < 128) d_Hout[dir][t][gk][gb] = hv;
    }
}

// ------------------------- output assembly (smem-tiled transpose) -------------------------
__global__ void __launch_bounds__(256) outk(float* __restrict__ out) {
    __shared__ float sm[256][33];
    const int tid = threadIdx.x, lane = tid & 31, wid = tid >> 5;
    const int bid = blockIdx.x;
    if (bid < 1024) {
        const int t = bid;
        const float* src = &d_Hout[0][t][0][0];
#pragma unroll 4
        for (int q = 0; q < 32; ++q) {
            int j = wid + 8 * q;
            sm[j][lane] = src[j * 32 + lane];
        }
        __syncthreads();
        for (int sq = 0; sq < 4; ++sq) {
            int sbv = wid * 4 + sq;
            int L = d_lens[sbv];
            float* dst = out + ((size_t)sbv * 1024 + t) * 512;
            if (t < L) {
#pragma unroll
                for (int q = 0; q < 8; ++q) dst[q * 32 + lane] = sm[q * 32 + lane][sbv];
            } else {
#pragma unroll
                for (int q = 0; q < 16; ++q) dst[q * 32 + lane] = 0.f;
            }
        }
    } else {
        const int s = bid - 1024;
        const float* src = &d_Hout[1][s][0][0];
#pragma unroll 4
        for (int q = 0; q < 32; ++q) {
            int j = wid + 8 * q;
            sm[j][lane] = src[j * 32 + lane];
        }
        __syncthreads();
        for (int sq = 0; sq < 4; ++sq) {
            int sbv = wid * 4 + sq;
            int L = d_lens[sbv];
            if (s < L) {
                int t = L - 1 - s;
                float* dst = out + ((size_t)sbv * 1024 + t) * 512 + 256;
#pragma unroll
                for (int q = 0; q < 8; ++q) dst[q * 32 + lane] = sm[q * 32 + lane][sbv];
            }
        }
    }
}

__global__ void tailk(float* __restrict__ out, int out_size) {
    int k = threadIdx.x;
    int idx = 16777216 + k;
    if (idx >= out_size) return;
    for (; idx < out_size; idx += 256, k += 256)
        out[idx] = (k < 32) ? (float)d_order[k] : 0.f;
}

// ------------------------- launch -------------------------
extern "C" void kernel_launch(void* const* d_in, const int* in_sizes, int n_in,
                              void* d_out, int out_size) {
    const float* x = (const float*)d_in[0];
    const int* xlen = (const int*)d_in[1];
    const float* W0 = (const float*)d_in[2];
    const float* b0 = (const float*)d_in[3];
    const float* W1 = (const float*)d_in[4];
    const float* b1 = (const float*)d_in[5];
    const float* W2 = (const float*)d_in[6];
    const float* b2 = (const float*)d_in[7];
    const float* Wih_f = (const float*)d_in[8];
    const float* Whh_f = (const float*)d_in[9];
    const float* bih_f = (const float*)d_in[10];
    const float* bhh_f = (const float*)d_in[11];
    const float* Wih_b = (const float*)d_in[12];
    const float* Whh_b = (const float*)d_in[13];
    const float* bih_b = (const float*)d_in[14];
    const float* bhh_b = (const float*)d_in[15];
    const float* h0 = (const float*)d_in[16];
    const float* c0 = (const float*)d_in[17];
    float* out = (float*)d_out;

    void *p_xh, *p_xl, *p_w0h, *p_w0l, *p_w1h, *p_w1l, *p_w2h, *p_w2l;
    void *p_wch, *p_wcl, *p_h, *p_Z, *p_bias;
    void *p_a0h, *p_a0l, *p_a1h, *p_a1l, *p_fh, *p_fl;
    cudaGetSymbolAddress(&p_h, d_h);
    cudaGetSymbolAddress(&p_Z, d_Z);
    cudaGetSymbolAddress(&p_bias, d_biascat);
    cudaGetSymbolAddress(&p_wch, d_Wch);
    cudaGetSymbolAddress(&p_wcl, d_Wcl);
    cudaGetSymbolAddress(&p_w1h, d_W1h);
    cudaGetSymbolAddress(&p_w1l, d_W1l);
    cudaGetSymbolAddress(&p_w2h, d_W2h);
    cudaGetSymbolAddress(&p_w2l, d_W2l);
    cudaGetSymbolAddress(&p_w0h, d_W0h);
    cudaGetSymbolAddress(&p_w0l, d_W0l);
    cudaGetSymbolAddress(&p_xh, d_Xh);
    cudaGetSymbolAddress(&p_xl, d_Xl);
    cudaGetSymbolAddress(&p_a0h, d_A0h);
    cudaGetSymbolAddress(&p_a0l, d_A0l);
    cudaGetSymbolAddress(&p_a1h, d_A1h);
    cudaGetSymbolAddress(&p_a1l, d_A1l);
    cudaGetSymbolAddress(&p_fh, d_Fh);
    cudaGetSymbolAddress(&p_fl, d_Fl);

    cudaFuncSetAttribute(gemm_mma_k<0, 0>, cudaFuncAttributeMaxDynamicSharedMemorySize, 98816);
    cudaFuncSetAttribute(gemm_mma_k<1, 0>, cudaFuncAttributeMaxDynamicSharedMemorySize, 98816);
    cudaFuncSetAttribute(gemm_mma_k<1, 1>, cudaFuncAttributeMaxDynamicSharedMemorySize, 98816);
    cudaFuncSetAttribute(lstm_rec_k, cudaFuncAttributeMaxDynamicSharedMemorySize, 36000);

    prep_k<<<512, 256>>>(x, xlen, W0, W1, W2, Wih_f, Wih_b, bih_f, bhh_f, bih_b, bhh_b);
    gemm_mma_k<1, 1><<<dim3(4, 256), 256, 98816>>>(
        (const uint16_t*)p_xh, (const uint16_t*)p_xl,
        (const uint16_t*)p_w0h, (const uint16_t*)p_w0l,
        b0, nullptr, (uint16_t*)p_a0h, (uint16_t*)p_a0l, 96, 512);
    gemm_mma_k<1, 1><<<dim3(4, 256), 256, 98816>>>(
        (const uint16_t*)p_a0h, (const uint16_t*)p_a0l,
        (const uint16_t*)p_w1h, (const uint16_t*)p_w1l,
        b1, nullptr, (uint16_t*)p_a1h, (uint16_t*)p_a1l, 512, 512);
    gemm_mma_k<1, 0><<<dim3(2, 256), 256, 98816>>>(
        (const uint16_t*)p_a1h, (const uint16_t*)p_a1l,
        (const uint16_t*)p_w2h, (const uint16_t*)p_w2l,
        b2, (float*)p_h, nullptr, nullptr, 512, 256);
    feat_k<<<8192, 256>>>();
    gemm_mma_k<0, 0><<<dim3(16, 256), 256, 98816>>>(
        (const uint16_t*)p_fh, (const uint16_t*)p_fl,
        (const uint16_t*)p_wch, (const uint16_t*)p_wcl,
        (const float*)p_bias, (float*)p_Z, nullptr, nullptr, 768, 2048);
    lstm_rec_k<<<128, 256, 36000>>>(Whh_f, Whh_b, h0, c0);
    outk<<<2048, 256>>>(out);
    tailk<<<1, 256>>>(out, out_size);
}

// round 17
// speedup vs baseline: 1.1583x; 1.0789x over previous
#include <cuda_runtime.h>
#include <cuda_fp16.h>
#include <math.h>
#include <stdint.h>
#include <string.h>

// B=32, T=1024, D_IN=80, enc: 80->512->512->256 (ReLU), F=768, 4H=1024, H=256

// ------------------------- device scratch -------------------------
__device__ float d_h[32768 * 256];
__device__ float d_Z[32768 * 2048];        // [b][t][2048]: cols 0..1023 fwd, 1024..2047 bwd
__device__ float d_biascat[2048];
__device__ uint4 d_Hfrag[2][2][2048];      // [parity][dir] mma A-fragments (fp16 hi/lo)
__device__ float d_Hout[2][1024][256][32]; // [dir][t][k][b]
__device__ int d_order[32];
__device__ int d_lens[32];
__device__ unsigned d_ctr2[2];
// converted weights + activations
__device__ uint16_t d_Wch[2048 * 768];                 // fp16 (hi only) for zgemm B
__device__ uint16_t d_W1h[512 * 512], d_W1l[512 * 512];   // bf16 pairs
__device__ uint16_t d_W2h[256 * 512], d_W2l[256 * 512];
__device__ uint16_t d_W0h[512 * 96], d_W0l[512 * 96];
__device__ uint16_t d_Xh[32768 * 96], d_Xl[32768 * 96];
__device__ uint16_t d_A0h[32768 * 512], d_A0l[32768 * 512];
__device__ uint16_t d_A1h[32768 * 512], d_A1l[32768 * 512];
__device__ uint16_t d_Fh[32768 * 768], d_Fl[32768 * 768]; // fp16 pairs for zgemm A

// ------------------------- helpers -------------------------
__device__ __forceinline__ uint32_t s2u(const void* p) {
    uint32_t a;
    asm("{ .reg .u64 t; cvta.to.shared.u64 t, %1; cvt.u32.u64 %0, t; }" : "=r"(a) : "l"(p));
    return a;
}
__device__ __forceinline__ uint32_t cvt2bf(float lo, float hi) {
    uint32_t r;
    asm("cvt.rn.satfinite.bf16x2.f32 %0, %1, %2;" : "=r"(r) : "f"(hi), "f"(lo));
    return r;
}
__device__ __forceinline__ void pack2(float x0, float x1, uint32_t& ph, uint32_t& pl) {
    ph = cvt2bf(x0, x1);
    float r0 = x0 - __uint_as_float(ph << 16);
    float r1 = x1 - __uint_as_float(ph & 0xffff0000u);
    pl = cvt2bf(r0, r1);
}
// fp16 pair split: hi = fp16(x), lo = fp16(x - hi)
__device__ __forceinline__ void pack2h(float x0, float x1, uint32_t& ph, uint32_t& pl) {
    __half2 h = __floats2half2_rn(x0, x1);
    ph = *(uint32_t*)&h;
    float r0 = x0 - __low2float(h);
    float r1 = x1 - __high2float(h);
    __half2 l = __floats2half2_rn(r0, r1);
    pl = *(uint32_t*)&l;
}
__device__ __forceinline__ void ldsm4(uint32_t* r, uint32_t addr) {
    asm volatile("ldmatrix.sync.aligned.m8n8.x4.shared.b16 {%0,%1,%2,%3}, [%4];"
                 : "=r"(r[0]), "=r"(r[1]), "=r"(r[2]), "=r"(r[3]) : "r"(addr));
}
__device__ __forceinline__ void mma16816(float* c, const uint32_t* a, uint32_t b0, uint32_t b1) {
    asm volatile(
        "mma.sync.aligned.m16n8k16.row.col.f32.bf16.bf16.f32 "
        "{%0,%1,%2,%3}, {%4,%5,%6,%7}, {%8,%9}, {%0,%1,%2,%3};"
        : "+f"(c[0]), "+f"(c[1]), "+f"(c[2]), "+f"(c[3])
        : "r"(a[0]), "r"(a[1]), "r"(a[2]), "r"(a[3]), "r"(b0), "r"(b1));
}
__device__ __forceinline__ void mma16816h(float* c, const uint32_t* a, uint32_t b0, uint32_t b1) {
    asm volatile(
        "mma.sync.aligned.m16n8k16.row.col.f32.f16.f16.f32 "
        "{%0,%1,%2,%3}, {%4,%5,%6,%7}, {%8,%9}, {%0,%1,%2,%3};"
        : "+f"(c[0]), "+f"(c[1]), "+f"(c[2]), "+f"(c[3])
        : "r"(a[0]), "r"(a[1]), "r"(a[2]), "r"(a[3]), "r"(b0), "r"(b1));
}
__device__ __forceinline__ void cpasync16(uint32_t smem_dst, const void* gsrc) {
    asm volatile("cp.async.cg.shared.global [%0], [%1], 16;"
                 :: "r"(smem_dst), "l"(gsrc) : "memory");
}
#define SWZB(row, c) ((((uint32_t)(row)) << 6) + ((((uint32_t)(c) ^ (((uint32_t)(row) >> 1) & 3))) << 4))

// write (f0,f1) for (b, k0, k0+1) as fp16 mma A-fragment (hi + lo residual)
__device__ __forceinline__ void write_fragh(int parity, int dir, int b, int k0, float f0, float f1) {
    uint32_t hi, lo;
    pack2h(f0, f1, hi, lo);
    int wd = k0 >> 5, kt = (k0 >> 4) & 1, jhi = (k0 >> 3) & 1, ll = (k0 >> 1) & 3;
    int mt = b >> 4, jlo = (b >> 3) & 1, L = (b & 7) * 4 + ll, j = jhi * 2 + jlo;
    uint32_t* H = (uint32_t*)&d_Hfrag[parity][dir][0];
    int base = ((wd * 2 + mt) * 2 + kt) * 2;
    H[(size_t)(((base + 0) * 32 + L) * 4 + j)] = hi;
    H[(size_t)(((base + 1) * 32 + L) * 4 + j)] = lo;
}

__device__ __forceinline__ void conv_range(const float* __restrict__ src,
                                           uint16_t* __restrict__ dh, uint16_t* __restrict__ dl,
                                           int npairs, int tid, int nth) {
    for (int i = tid; i < npairs; i += nth) {
        float2 v = ((const float2*)src)[i];
        uint32_t ph, pl;
        pack2(v.x, v.y, ph, pl);
        ((uint32_t*)dh)[i] = ph;
        ((uint32_t*)dl)[i] = pl;
    }
}

// fp16 hi-only conversion
__device__ __forceinline__ void conv_h(const float* __restrict__ src,
                                       uint16_t* __restrict__ dh, int npairs, int tid, int nth) {
    for (int i = tid; i < npairs; i += nth) {
        float2 v = ((const float2*)src)[i];
        __half2 h = __floats2half2_rn(v.x, v.y);
        ((uint32_t*)dh)[i] = *(uint32_t*)&h;
    }
}

__device__ __forceinline__ void conv_pad(const float* __restrict__ src,
                                         uint16_t* __restrict__ dh, uint16_t* __restrict__ dl,
                                         int rows, int kreal, int kpad2, int tid, int nth) {
    const int rp = kreal >> 1;
    for (int i = tid; i < rows * kpad2; i += nth) {
        int row = i / kpad2, cp = i % kpad2;
        uint32_t ph = 0, pl = 0;
        if (cp < rp) {
            float2 v = *(const float2*)(src + (size_t)row * kreal + cp * 2);
            pack2(v.x, v.y, ph, pl);
        }
        ((uint32_t*)dh)[i] = ph;
        ((uint32_t*)dl)[i] = pl;
    }
}

// ------------------------- prep: order, biascat, all conversions -------------------------
__global__ void __launch_bounds__(256) prep_k(
    const float* __restrict__ x, const int* __restrict__ xlen,
    const float* __restrict__ W0, const float* __restrict__ W1, const float* __restrict__ W2,
    const float* __restrict__ Wihf, const float* __restrict__ Wihb,
    const float* __restrict__ bihf, const float* __restrict__ bhhf,
    const float* __restrict__ bihb, const float* __restrict__ bhhb) {
    const int ptid = blockIdx.x * 256 + threadIdx.x;
    const int nth = gridDim.x * 256;
    if (ptid == 0) {
        unsigned used = 0;
        for (int p = 0; p < 32; ++p) {
            int best = -1, bl = -2147483647;
            for (int j = 0; j < 32; ++j) {
                if (used & (1u << j)) continue;
                int L = xlen[j];
                if (L > bl) { bl = L; best = j; }
            }
            used |= (1u << best);
            d_order[p] = best;
            d_lens[p] = bl;
        }
        d_ctr2[0] = 0u;
        d_ctr2[1] = 0u;
    }
    if (ptid < 1024) d_biascat[ptid] = bihf[ptid] + bhhf[ptid];
    else if (ptid < 2048) d_biascat[ptid] = bihb[ptid - 1024] + bhhb[ptid - 1024];
    conv_pad(x, d_Xh, d_Xl, 32768, 80, 48, ptid, nth);
    conv_pad(W0, d_W0h, d_W0l, 512, 80, 48, ptid, nth);
    conv_range(W1, d_W1h, d_W1l, 131072, ptid, nth);
    conv_range(W2, d_W2h, d_W2l, 65536, ptid, nth);
    conv_h(Wihf, d_Wch, 393216, ptid, nth);
    conv_h(Wihb, d_Wch + 1024 * 768, 393216, ptid, nth);
}

// ------------------------- HMMA split GEMM (3-stage cp.async, 2 CTAs/SM) ------------------
// F16=0: bf16 3-term (A hi/lo, B hi/lo).  F16=1: fp16 2-term (A hi/lo, B hi only).
template <int RELU, int OUTBF, int F16>
__global__ void __launch_bounds__(256, 2) gemm_mma_k(
    const uint16_t* __restrict__ Ahi, const uint16_t* __restrict__ Alo,
    const uint16_t* __restrict__ Bhi, const uint16_t* __restrict__ Blo,
    const float* __restrict__ bias, float* __restrict__ Cf,
    uint16_t* __restrict__ Chi, uint16_t* __restrict__ Clo,
    int K, int ldo) {
    extern __shared__ char smc[];
    const int CB = F16 ? 24576 : 32768;  // chunk bytes
    const int tid = threadIdx.x, lane = tid & 31, wid = tid >> 5;
    const int wm = wid >> 2, wn = wid & 3;
    const int n0 = blockIdx.x * 128, m0 = blockIdx.y * 128;
    const int NCH = K >> 5;
    const uint32_t sbase = s2u(smc);
    float* sBias = (float*)(smc + 3 * CB);
    if (tid < 128) sBias[tid] = bias[n0 + tid];

    const int ra = tid >> 2, ca = tid & 3;
    const int ldu = K >> 3;
    const uint4* Ah0 = (const uint4*)Ahi + (size_t)(m0 + ra) * ldu + ca;
    const uint4* Al0 = (const uint4*)Alo + (size_t)(m0 + ra) * ldu + ca;
    const uint4* Ah1 = (const uint4*)Ahi + (size_t)(m0 + 64 + ra) * ldu + ca;
    const uint4* Al1 = (const uint4*)Alo + (size_t)(m0 + 64 + ra) * ldu + ca;
    const uint4* Bh0 = (const uint4*)Bhi + (size_t)(n0 + ra) * ldu + ca;
    const uint4* Bh1 = (const uint4*)Bhi + (size_t)(n0 + 64 + ra) * ldu + ca;
    const uint4* Bl0 = (const uint4*)Blo + (size_t)(n0 + ra) * ldu + ca;
    const uint4* Bl1 = (const uint4*)Blo + (size_t)(n0 + 64 + ra) * ldu + ca;

    float acc[4][4][4];
#pragma unroll
    for (int mi = 0; mi < 4; mi++)
#pragma unroll
        for (int j = 0; j < 4; j++)
#pragma unroll
            for (int q = 0; q < 4; q++) acc[mi][j][q] = 0.f;

    const uint32_t o0 = SWZB(ra, ca), o1 = SWZB(64 + ra, ca);
#define ISSUE_CHUNK(ci, bufi)                                     \
    do {                                                          \
        const int ku_ = (ci) << 2;                                \
        uint32_t base_ = sbase + (bufi) * CB;                     \
        cpasync16(base_ + o0, Ah0 + ku_);                         \
        cpasync16(base_ + 8192 + o0, Al0 + ku_);                  \
        cpasync16(base_ + o1, Ah1 + ku_);                         \
        cpasync16(base_ + 8192 + o1, Al1 + ku_);                  \
        cpasync16(base_ + 16384 + o0, Bh0 + ku_);                 \
        cpasync16(base_ + 16384 + o1, Bh1 + ku_);                 \
        if (!F16) {                                               \
            cpasync16(base_ + 24576 + o0, Bl0 + ku_);             \
            cpasync16(base_ + 24576 + o1, Bl1 + ku_);             \
        }                                                         \
        asm volatile("cp.async.commit_group;" ::: "memory");      \
    } while (0)

    ISSUE_CHUNK(0, 0);
    if (NCH > 1) ISSUE_CHUNK(1, 1);

    int buf = 0;
    for (int i = 0; i < NCH; ++i) {
        __syncthreads();
        if (i + 2 < NCH) {
            int b2 = buf + 2;
            if (b2 >= 3) b2 -= 3;
            ISSUE_CHUNK(i + 2, b2);
            asm volatile("cp.async.wait_group 2;" ::: "memory");
        } else if (i + 1 < NCH) {
            asm volatile("cp.async.wait_group 1;" ::: "memory");
        } else {
            asm volatile("cp.async.wait_group 0;" ::: "memory");
        }
        __syncthreads();
        const uint32_t ab = sbase + buf * CB;
        const uint32_t bb = ab + 16384;
#pragma unroll
        for (int ks = 0; ks < 2; ++ks) {
            const int r = lane & 15;
            const int cu = (ks << 1) + (lane >> 4);
            uint32_t ah[4][4], al[4][4], bh[2][4], bl[2][4];
#pragma unroll
            for (int mi = 0; mi < 4; ++mi) {
                uint32_t off = SWZB(wm * 64 + mi * 16 + r, cu);
                ldsm4(ah[mi], ab + off);
                ldsm4(al[mi], ab + 8192 + off);
            }
#pragma unroll
            for (int ni = 0; ni < 2; ++ni) {
                uint32_t off = SWZB(wn * 32 + ni * 16 + r, cu);
                ldsm4(bh[ni], bb + off);
                if (!F16) ldsm4(bl[ni], ab + 24576 + off);
            }
#pragma unroll
            for (int mi = 0; mi < 4; ++mi)
#pragma unroll
                for (int j = 0; j < 4; ++j) {
                    const int ni = j >> 1, s = j & 1;
                    if (F16) {
                        mma16816h(acc[mi][j], ah[mi], bh[ni][s], bh[ni][s + 2]);
                        mma16816h(acc[mi][j], al[mi], bh[ni][s], bh[ni][s + 2]);
                    } else {
                        mma16816(acc[mi][j], ah[mi], bh[ni][s], bh[ni][s + 2]);
                        mma16816(acc[mi][j], al[mi], bh[ni][s], bh[ni][s + 2]);
                        mma16816(acc[mi][j], ah[mi], bl[ni][s], bl[ni][s + 2]);
                    }
                }
        }
        if (++buf == 3) buf = 0;
    }
#undef ISSUE_CHUNK

#pragma unroll
    for (int mi = 0; mi < 4; ++mi)
#pragma unroll
        for (int j = 0; j < 4; ++j) {
            const int row = m0 + wm * 64 + mi * 16 + (lane >> 2);
            const int colL = wn * 32 + j * 8 + (lane & 3) * 2;
            const float b0v = sBias[colL], b1v = sBias[colL + 1];
            float x0 = acc[mi][j][0] + b0v, x1 = acc[mi][j][1] + b1v;
            float x2 = acc[mi][j][2] + b0v, x3 = acc[mi][j][3] + b1v;
            if (RELU) {
                x0 = fmaxf(x0, 0.f); x1 = fmaxf(x1, 0.f);
                x2 = fmaxf(x2, 0.f); x3 = fmaxf(x3, 0.f);
            }
            if (OUTBF) {
                uint32_t ph, pl;
                pack2(x0, x1, ph, pl);
                *(uint32_t*)(Chi + (size_t)row * ldo + n0 + colL) = ph;
                *(uint32_t*)(Clo + (size_t)row * ldo + n0 + colL) = pl;
                pack2(x2, x3, ph, pl);
                *(uint32_t*)(Chi + (size_t)(row + 8) * ldo + n0 + colL) = ph;
                *(uint32_t*)(Clo + (size_t)(row + 8) * ldo + n0 + colL) = pl;
            } else {
                *(float2*)(Cf + (size_t)row * ldo + n0 + colL) = make_float2(x0, x1);
                *(float2*)(Cf + (size_t)(row + 8) * ldo + n0 + colL) = make_float2(x2, x3);
            }
        }
}

// ------------------------- fused deltas(2x) + feat assembly -> fp16 hi/lo ------------------------
__device__ __forceinline__ float4 d1_at(const float4* __restrict__ h4, size_t base, int t, int c4) {
    int tp1 = min(t + 1, 1023), tm1 = max(t - 1, 0);
    int tp2 = min(t + 2, 1023), tm2 = max(t - 2, 0);
    float4 a = h4[base + (size_t)tp1 * 64 + c4];
    float4 b = h4[base + (size_t)tm1 * 64 + c4];
    float4 c = h4[base + (size_t)tp2 * 64 + c4];
    float4 d = h4[base + (size_t)tm2 * 64 + c4];
    float4 z;
    z.x = (a.x - b.x) * 0.5f + (c.x - d.x) * 0.25f;
    z.y = (a.y - b.y) * 0.5f + (c.y - d.y) * 0.25f;
    z.z = (a.z - b.z) * 0.5f + (c.z - d.z) * 0.25f;
    z.w = (a.w - b.w) * 0.5f + (c.w - d.w) * 0.25f;
    return z;
}

__global__ void feat_k() {
    int idx = blockIdx.x * 256 + threadIdx.x;
    if (idx >= 32 * 1024 * 64) return;
    int c4 = idx & 63, t = (idx >> 6) & 1023, sb = idx >> 16;
    int b = d_order[sb];
    const float4* h4 = (const float4*)d_h;
    size_t base = (size_t)b * 65536;
    float4 hv = h4[base + (size_t)t * 64 + c4];
    float4 d1v = d1_at(h4, base, t, c4);
    int tp1 = min(t + 1, 1023), tm1 = max(t - 1, 0);
    int tp2 = min(t + 2, 1023), tm2 = max(t - 2, 0);
    float4 a = d1_at(h4, base, tp1, c4);
    float4 bb = d1_at(h4, base, tm1, c4);
    float4 c = d1_at(h4, base, tp2, c4);
    float4 d = d1_at(h4, base, tm2, c4);
    float4 d2v;
    d2v.x = (a.x - bb.x) * 0.5f + (c.x - d.x) * 0.25f;
    d2v.y = (a.y - bb.y) * 0.5f + (c.y - d.y) * 0.25f;
    d2v.z = (a.z - bb.z) * 0.5f + (c.z - d.z) * 0.25f;
    d2v.w = (a.w - bb.w) * 0.5f + (c.w - d.w) * 0.25f;
    uint32_t* Fh32 = (uint32_t*)d_Fh;
    uint32_t* Fl32 = (uint32_t*)d_Fl;
    size_t ob = ((size_t)sb * 1024 + t) * 384;
    uint2 hp, lp;
    pack2h(hv.x, hv.y, hp.x, lp.x);
    pack2h(hv.z, hv.w, hp.y, lp.y);
    *(uint2*)&Fh32[ob + c4 * 2] = hp;
    *(uint2*)&Fl32[ob + c4 * 2] = lp;
    pack2h(d1v.x, d1v.y, hp.x, lp.x);
    pack2h(d1v.z, d1v.w, hp.y, lp.y);
    *(uint2*)&Fh32[ob + 128 + c4 * 2] = hp;
    *(uint2*)&Fl32[ob + 128 + c4 * 2] = lp;
    pack2h(d2v.x, d2v.y, hp.x, lp.x);
    pack2h(d2v.z, d2v.w, hp.y, lp.y);
    *(uint2*)&Fh32[ob + 256 + c4 * 2] = hp;
    *(uint2*)&Fl32[ob + 256 + c4 * 2] = lp;
}

// ------------------------- persistent bidirectional LSTM recurrence (fp16 2-term) -----------------
// R13 structure exactly; W as fp16 hi only (registers), h as fp16 hi/lo fragments.
// smem: W-stage 8K (init only) | P 17408 | zs 2112
__global__ void __launch_bounds__(256, 1) lstm_rec_k(
    const float* __restrict__ Whh_f, const float* __restrict__ Whh_b,
    const float* __restrict__ h0, const float* __restrict__ c0) {
    extern __shared__ char smc[];
    const int POFF = 8192, ZOFF = POFF + 17408;
    float* P = (float*)(smc + POFF);
    float* zs = (float*)(smc + ZOFF);
    const uint32_t sb = s2u(smc);
    const int tid = threadIdx.x, lane = tid & 31, wid = tid >> 5;
    const int dir = blockIdx.x >> 6, slice = blockIdx.x & 63;
    const float* Whh = dir ? Whh_b : Whh_f;

    // stage W slice into smem as fp16 (ldsm layout), init only
    for (int i = tid; i < 4096; i += 256) {
        int r = i >> 8, k = i & 255;
        int grow = ((r >> 2) << 8) + (slice << 2) + (r & 3);
        float w = __ldg(Whh + (size_t)grow * 256 + k);
        __half hw = __float2half_rn(w);
        int c = k >> 3;
        int phys = (c & 24) | ((c ^ r) & 7);
        int off = r * 512 + phys * 16 + (k & 7) * 2;
        *(uint16_t*)(smc + off) = *(uint16_t*)&hw;
    }
    __syncthreads();
    // B fragments into registers (loop-invariant)
    const int rr = lane & 15, hs = lane >> 4;
    uint32_t bfh[2][4];
#pragma unroll
    for (int kt = 0; kt < 2; ++kt) {
        int cu = wid * 4 + kt * 2 + hs;
        int phys = (cu & 24) | ((cu ^ rr) & 7);
        uint32_t off = (uint32_t)(rr * 512 + phys * 16);
        ldsm4(bfh[kt], sb + off);
    }

    // gate mapping: tid<128: gb = tid>>2, gj = tid&3; k = slice*4 + gj
    const int gb = tid >> 2, gj = tid & 3;
    const int gk = (slice << 2) + gj;
    float creg = 0.f;
    int Lb = 0;
    if (tid < 128) {
        Lb = d_lens[tid & 31];
        creg = c0[(dir * 32 + gb) * 256 + gk];
        float f = h0[(dir * 32 + gb) * 256 + gk];
        float f1 = __shfl_xor_sync(0xffffffffu, f, 1);
        if ((gj & 1) == 0) write_fragh(0, dir, gb, gk, f, f1);
    }
    __syncthreads();
    if (tid == 0)
        asm volatile("red.release.gpu.global.add.u32 [%0], %1;"
                     :: "l"(&d_ctr2[dir]), "r"(1u) : "memory");

    for (int t = 0; t < 1024; ++t) {
        // Z prefetch: latency hides under spin
        float4 zv;
        int zg = tid >> 5, zb = tid & 31;
        if (tid < 128) {
            int tt = dir ? max(Lb - 1 - t, 0) : t;
            const float* zp = d_Z + ((size_t)zb * 1024 + tt) * 2048 + dir * 1024 + (slice << 2) + (zg << 8);
            zv = *(const float4*)zp;
        }
        if (tid == 0) {
            unsigned tgt = 64u * (unsigned)(t + 1), v;
            do {
                asm volatile("ld.acquire.gpu.global.u32 %0, [%1];"
                             : "=r"(v) : "l"(&d_ctr2[dir]) : "memory");
            } while (v < tgt);
        }
        __syncthreads();
        if (tid < 128) {
            zs[(0 * 4 + zg) * 33 + zb] = zv.x;
            zs[(1 * 4 + zg) * 33 + zb] = zv.y;
            zs[(2 * 4 + zg) * 33 + zb] = zv.z;
            zs[(3 * 4 + zg) * 33 + zb] = zv.w;
        }
        uint32_t ahr[2][2][4], alr[2][2][4];
        {
            const uint4* hf = &d_Hfrag[t & 1][dir][0];
#pragma unroll
            for (int mt = 0; mt < 2; ++mt)
#pragma unroll
                for (int kt = 0; kt < 2; ++kt) {
                    int u4 = (((wid * 2 + mt) * 2 + kt) * 2) * 32 + lane;
                    uint4 v = __ldcg(hf + u4);
                    ahr[mt][kt][0] = v.x; ahr[mt][kt][1] = v.y;
                    ahr[mt][kt][2] = v.z; ahr[mt][kt][3] = v.w;
                    v = __ldcg(hf + u4 + 32);
                    alr[mt][kt][0] = v.x; alr[mt][kt][1] = v.y;
                    alr[mt][kt][2] = v.z; alr[mt][kt][3] = v.w;
                }
        }
        float acc[2][2][4];
#pragma unroll
        for (int a = 0; a < 2; a++)
#pragma unroll
            for (int bq = 0; bq < 2; bq++)
#pragma unroll
                for (int q2 = 0; q2 < 4; q2++) acc[a][bq][q2] = 0.f;
#pragma unroll
        for (int mt = 0; mt < 2; ++mt)
#pragma unroll
            for (int nt = 0; nt < 2; ++nt)
#pragma unroll
                for (int kt = 0; kt < 2; ++kt) {
                    mma16816h(acc[mt][nt], ahr[mt][kt], bfh[kt][nt], bfh[kt][nt + 2]);
                    mma16816h(acc[mt][nt], alr[mt][kt], bfh[kt][nt], bfh[kt][nt + 2]);
                }
#pragma unroll
        for (int mt = 0; mt < 2; ++mt)
#pragma unroll
            for (int nt = 0; nt < 2; ++nt) {
                int b = mt * 16 + (lane >> 2);
                int r = nt * 8 + (lane & 3) * 2;
                P[(wid * 32 + b) * 17 + r] = acc[mt][nt][0];
                P[(wid * 32 + b) * 17 + r + 1] = acc[mt][nt][1];
                P[(wid * 32 + b + 8) * 17 + r] = acc[mt][nt][2];
                P[(wid * 32 + b + 8) * 17 + r + 1] = acc[mt][nt][3];
            }
        __syncthreads();
        float hv = 0.f;
        if (tid < 128) {
            float g4[4];
#pragma unroll
            for (int g = 0; g < 4; ++g) {
                float s = zs[(gj * 4 + g) * 33 + gb];
                int ri = 4 * g + gj;
#pragma unroll
                for (int w8 = 0; w8 < 8; ++w8) s += P[(w8 * 32 + gb) * 17 + ri];
                g4[g] = s;
            }
            float is = 1.f / (1.f + expf(-g4[0]));
            float fs = 1.f / (1.f + expf(-g4[1]));
            float gt = tanhf(g4[2]);
            float os = 1.f / (1.f + expf(-g4[3]));
            creg = fs * creg + is * gt;
            hv = os * tanhf(creg);
            float hv1 = __shfl_xor_sync(0xffffffffu, hv, 1);
            if ((gj & 1) == 0) write_fragh((t + 1) & 1, dir, gb, gk, hv, hv1);
        }
        __syncthreads();
        if (tid == 0)
            asm volatile("red.release.gpu.global.add.u32 [%0], %1;"
                         :: "l"(&d_ctr2[dir]), "r"(1u) : "memory");
        if (tid < 128) d_Hout[dir][t][gk][gb] = hv;
    }
}

// ------------------------- output assembly (smem-tiled transpose) -------------------------
__global__ void __launch_bounds__(256) outk(float* __restrict__ out) {
    __shared__ float sm[256][33];
    const int tid = threadIdx.x, lane = tid & 31, wid = tid >> 5;
    const int bid = blockIdx.x;
    if (bid < 1024) {
        const int t = bid;
        const float* src = &d_Hout[0][t][0][0];
#pragma unroll 4
        for (int q = 0; q < 32; ++q) {
            int j = wid + 8 * q;
            sm[j][lane] = src[j * 32 + lane];
        }
        __syncthreads();
        for (int sq = 0; sq < 4; ++sq) {
            int sbv = wid * 4 + sq;
            int L = d_lens[sbv];
            float* dst = out + ((size_t)sbv * 1024 + t) * 512;
            if (t < L) {
#pragma unroll
                for (int q = 0; q < 8; ++q) dst[q * 32 + lane] = sm[q * 32 + lane][sbv];
            } else {
#pragma unroll
                for (int q = 0; q < 16; ++q) dst[q * 32 + lane] = 0.f;
            }
        }
    } else {
        const int s = bid - 1024;
        const float* src = &d_Hout[1][s][0][0];
#pragma unroll 4
        for (int q = 0; q < 32; ++q) {
            int j = wid + 8 * q;
            sm[j][lane] = src[j * 32 + lane];
        }
        __syncthreads();
        for (int sq = 0; sq < 4; ++sq) {
            int sbv = wid * 4 + sq;
            int L = d_lens[sbv];
            if (s < L) {
                int t = L - 1 - s;
                float* dst = out + ((size_t)sbv * 1024 + t) * 512 + 256;
#pragma unroll
                for (int q = 0; q < 8; ++q) dst[q * 32 + lane] = sm[q * 32 + lane][sbv];
            }
        }
    }
}

__global__ void tailk(float* __restrict__ out, int out_size) {
    int k = threadIdx.x;
    int idx = 16777216 + k;
    if (idx >= out_size) return;
    for (; idx < out_size; idx += 256, k += 256)
        out[idx] = (k < 32) ? (float)d_order[k] : 0.f;
}

// ------------------------- launch -------------------------
extern "C" void kernel_launch(void* const* d_in, const int* in_sizes, int n_in,
                              void* d_out, int out_size) {
    const float* x = (const float*)d_in[0];
    const int* xlen = (const int*)d_in[1];
    const float* W0 = (const float*)d_in[2];
    const float* b0 = (const float*)d_in[3];
    const float* W1 = (const float*)d_in[4];
    const float* b1 = (const float*)d_in[5];
    const float* W2 = (const float*)d_in[6];
    const float* b2 = (const float*)d_in[7];
    const float* Wih_f = (const float*)d_in[8];
    const float* Whh_f = (const float*)d_in[9];
    const float* bih_f = (const float*)d_in[10];
    const float* bhh_f = (const float*)d_in[11];
    const float* Wih_b = (const float*)d_in[12];
    const float* Whh_b = (const float*)d_in[13];
    const float* bih_b = (const float*)d_in[14];
    const float* bhh_b = (const float*)d_in[15];
    const float* h0 = (const float*)d_in[16];
    const float* c0 = (const float*)d_in[17];
    float* out = (float*)d_out;

    void *p_xh, *p_xl, *p_w0h, *p_w0l, *p_w1h, *p_w1l, *p_w2h, *p_w2l;
    void *p_wch, *p_h, *p_Z, *p_bias;
    void *p_a0h, *p_a0l, *p_a1h, *p_a1l, *p_fh, *p_fl;
    cudaGetSymbolAddress(&p_h, d_h);
    cudaGetSymbolAddress(&p_Z, d_Z);
    cudaGetSymbolAddress(&p_bias, d_biascat);
    cudaGetSymbolAddress(&p_wch, d_Wch);
    cudaGetSymbolAddress(&p_w1h, d_W1h);
    cudaGetSymbolAddress(&p_w1l, d_W1l);
    cudaGetSymbolAddress(&p_w2h, d_W2h);
    cudaGetSymbolAddress(&p_w2l, d_W2l);
    cudaGetSymbolAddress(&p_w0h, d_W0h);
    cudaGetSymbolAddress(&p_w0l, d_W0l);
    cudaGetSymbolAddress(&p_xh, d_Xh);
    cudaGetSymbolAddress(&p_xl, d_Xl);
    cudaGetSymbolAddress(&p_a0h, d_A0h);
    cudaGetSymbolAddress(&p_a0l, d_A0l);
    cudaGetSymbolAddress(&p_a1h, d_A1h);
    cudaGetSymbolAddress(&p_a1l, d_A1l);
    cudaGetSymbolAddress(&p_fh, d_Fh);
    cudaGetSymbolAddress(&p_fl, d_Fl);

    cudaFuncSetAttribute(gemm_mma_k<0, 0, 1>, cudaFuncAttributeMaxDynamicSharedMemorySize, 74240);
    cudaFuncSetAttribute(gemm_mma_k<1, 0, 0>, cudaFuncAttributeMaxDynamicSharedMemorySize, 98816);
    cudaFuncSetAttribute(gemm_mma_k<1, 1, 0>, cudaFuncAttributeMaxDynamicSharedMemorySize, 98816);
    cudaFuncSetAttribute(lstm_rec_k, cudaFuncAttributeMaxDynamicSharedMemorySize, 28000);

    prep_k<<<512, 256>>>(x, xlen, W0, W1, W2, Wih_f, Wih_b, bih_f, bhh_f, bih_b, bhh_b);
    // encoder: bf16 3-term (proven precision)
    gemm_mma_k<1, 1, 0><<<dim3(4, 256), 256, 98816>>>(
        (const uint16_t*)p_xh, (const uint16_t*)p_xl,
        (const uint16_t*)p_w0h, (const uint16_t*)p_w0l,
        b0, nullptr, (uint16_t*)p_a0h, (uint16_t*)p_a0l, 96, 512);
    gemm_mma_k<1, 1, 0><<<dim3(4, 256), 256, 98816>>>(
        (const uint16_t*)p_a0h, (const uint16_t*)p_a0l,
        (const uint16_t*)p_w1h, (const uint16_t*)p_w1l,
        b1, nullptr, (uint16_t*)p_a1h, (uint16_t*)p_a1l, 512, 512);
    gemm_mma_k<1, 0, 0><<<dim3(2, 256), 256, 98816>>>(
        (const uint16_t*)p_a1h, (const uint16_t*)p_a1l,
        (const uint16_t*)p_w2h, (const uint16_t*)p_w2l,
        b2, (float*)p_h, nullptr, nullptr, 512, 256);
    feat_k<<<8192, 256>>>();
    // zgemm: fp16 2-term (B hi only)
    gemm_mma_k<0, 0, 1><<<dim3(16, 256), 256, 74240>>>(
        (const uint16_t*)p_fh, (const uint16_t*)p_fl,
        (const uint16_t*)p_wch, (const uint16_t*)p_wch,
        (const float*)p_bias, (float*)p_Z, nullptr, nullptr, 768, 2048);
    lstm_rec_k<<<128, 256, 28000>>>(Whh_f, Whh_b, h0, c0);
    outk<<<2048, 256>>>(out);
    tailk<<<1, 256>>>(out, out_size);
}